// round 5
// baseline (speedup 1.0000x reference)
#include <cuda_runtime.h>
#include <cstddef>

// ---------------- problem constants ----------------
#define BB   64
#define TT   1024
#define II   128
#define HH   512
#define KK   640            // I + H
#define G4H  2048

// ---------------- partitioning ----------------
#define GH   32             // hidden groups
#define GB   4              // batch groups
#define NCTA (GH*GB)        // 128 CTAs, one per SM, all resident (<=148)
#define UH   16             // hidden units per CTA
#define UB   16             // batches per CTA
#define NTHR 128            // threads per CTA: 16 j x 8 batch-pairs

#define WST  642            // smem row stride (floats): even (f32x2 aligned), 2-bank shift/row -> conflict free
#define HXST 642

typedef unsigned long long ull;

// persistent state (no cudaMalloc allowed)
__device__ float        g_Hbuf[2][BB*HH];
__device__ unsigned int g_bar;

// ---------------- packed fp32x2 helpers (Blackwell) ----------------
__device__ __forceinline__ ull ffma2(ull a, ull b, ull c) {
    ull d;
    asm("fma.rn.f32x2 %0, %1, %2, %3;" : "=l"(d) : "l"(a), "l"(b), "l"(c));
    return d;
}
__device__ __forceinline__ ull pack2(float lo, float hi) {
    ull d; asm("mov.b64 %0, {%1, %2};" : "=l"(d) : "f"(lo), "f"(hi)); return d;
}
__device__ __forceinline__ float red2(ull v) {
    return __uint_as_float((unsigned)v) + __uint_as_float((unsigned)(v >> 32));
}
__device__ __forceinline__ float sigm(float x) { return 1.0f / (1.0f + expf(-x)); }

__device__ __forceinline__ unsigned ld_acq(const unsigned* p) {
    unsigned v;
    asm volatile("ld.acquire.gpu.global.u32 %0, [%1];" : "=r"(v) : "l"(p) : "memory");
    return v;
}

__global__ void slstm_init_kernel() { g_bar = 0u; }

// ---------------- persistent sLSTM kernel ----------------
extern "C" __global__ void __launch_bounds__(NTHR, 1)
sLSTM_70772471103948_kernel(const float* __restrict__ x,     // [B,T,I]
                            const float* __restrict__ W_ih,  // [4H,I]
                            const float* __restrict__ W_hh,  // [4H,H]
                            const float* __restrict__ b_ih,  // [4H]
                            const float* __restrict__ b_hh,  // [4H]
                            const float* __restrict__ Wf,    // [H,H]
                            const float* __restrict__ bf,    // [H]
                            float* __restrict__ out,         // [B,T,H] | h[B,H] | c[B,H]
                            long long out_elems)
{
    extern __shared__ float smem[];
    float* Wsm = smem;                   // 64 rows (4 gates x 16 units) x WST
    float* hx  = smem + 64 * WST;        // 16 batches x HXST ([x_t | h_t])

    const int tid = threadIdx.x;
    const int u   = tid & 15;            // local hidden unit
    const int bp  = tid >> 4;            // batch pair id 0..7
    const int hg  = blockIdx.x & (GH - 1);
    const int bg  = blockIdx.x >> 5;
    const int j0  = hg * UH;
    const int b0  = bg * UB;
    const int j   = j0 + u;              // global hidden index
    const int blo = bp, bhi = bp + 8;    // local batches owned by this thread
    const int gblo = b0 + blo, gbhi = b0 + bhi;

    // ---- stage gate weights into SMEM once (resident for all 1024 steps) ----
    for (int idx = tid; idx < 64 * KK; idx += NTHR) {
        int r  = idx / KK;
        int k  = idx - r * KK;
        int gg = r >> 4, uu = r & 15;
        int grow = gg * HH + j0 + uu;            // gate order: i,f,g,o
        float w = (k < II) ? W_ih[grow * II + k] : W_hh[grow * HH + (k - II)];
        Wsm[r * WST + k] = w;
    }
    // ---- stage x_0 ; h_0 = 0 ----
    for (int idx = tid; idx < UB * II; idx += NTHR) {
        int b = idx >> 7, k = idx & 127;
        hx[b * HXST + k] = x[((size_t)(b0 + b) * TT + 0) * II + k];
    }
    for (int idx = tid; idx < UB * HH; idx += NTHR) {
        int b = idx >> 9, k = idx & 511;
        hx[b * HXST + II + k] = 0.0f;
    }
    // per-thread biases
    float bias0 = b_ih[0 * HH + j] + b_hh[0 * HH + j];
    float bias1 = b_ih[1 * HH + j] + b_hh[1 * HH + j];
    float bias2 = b_ih[2 * HH + j] + b_hh[2 * HH + j];
    float bias3 = b_ih[3 * HH + j] + b_hh[3 * HH + j];
    const float bfj = bf[j];

    __syncthreads();

    const ull* wiR  = (const ull*)(Wsm + (0 * 16 + u) * WST);
    const ull* wfR  = (const ull*)(Wsm + (1 * 16 + u) * WST);
    const ull* wgR  = (const ull*)(Wsm + (2 * 16 + u) * WST);
    const ull* woR  = (const ull*)(Wsm + (3 * 16 + u) * WST);
    const ull* hloR = (const ull*)(hx + blo * HXST);
    const ull* hhiR = (const ull*)(hx + bhi * HXST);
    const ull* hloH = (const ull*)(hx + blo * HXST + II);
    const ull* hhiH = (const ull*)(hx + bhi * HXST + II);
    const float4* wfrow = (const float4*)(Wf + (size_t)j * HH);

    float c_lo = 0.f, c_hi = 0.f, h_lo = 0.f, h_hi = 0.f;

    #pragma unroll 1
    for (int t = 0; t < TT; t++) {
        // ===== phase 1: gate GEMM (k packed in fp32x2) + cell/hidden update =====
        ull ai0 = 0, af0 = 0, ag0 = 0, ao0 = 0;
        ull ai1 = 0, af1 = 0, ag1 = 0, ao1 = 0;
        #pragma unroll 4
        for (int kk = 0; kk < KK / 2; kk++) {
            ull v0 = hloR[kk];
            ull v1 = hhiR[kk];
            ull w0 = wiR[kk], w1 = wfR[kk], w2 = wgR[kk], w3 = woR[kk];
            ai0 = ffma2(w0, v0, ai0);  ai1 = ffma2(w0, v1, ai1);
            af0 = ffma2(w1, v0, af0);  af1 = ffma2(w1, v1, af1);
            ag0 = ffma2(w2, v0, ag0);  ag1 = ffma2(w2, v1, ag1);
            ao0 = ffma2(w3, v0, ao0);  ao1 = ffma2(w3, v1, ao1);
        }
        {
            float gi = red2(ai0) + bias0, gf = red2(af0) + bias1;
            float gg = red2(ag0) + bias2, go = red2(ao0) + bias3;
            float iv = sigm(gi), fv = sigm(gf), gv = tanhf(gg), ov = sigm(go);
            c_lo = fv * c_lo + iv * gv;
            h_lo = ov * tanhf(c_lo);
        }
        {
            float gi = red2(ai1) + bias0, gf = red2(af1) + bias1;
            float gg = red2(ag1) + bias2, go = red2(ao1) + bias3;
            float iv = sigm(gi), fv = sigm(gf), gv = tanhf(gg), ov = sigm(go);
            c_hi = fv * c_hi + iv * gv;
            h_hi = ov * tanhf(c_hi);
        }

        const int p1 = (t + 1) & 1;
        out[((size_t)gblo * TT + t) * HH + j] = h_lo;
        out[((size_t)gbhi * TT + t) * HH + j] = h_hi;
        __stcg(&g_Hbuf[p1][gblo * HH + j], h_lo);
        __stcg(&g_Hbuf[p1][gbhi * HH + j], h_hi);

        // ===== grid barrier (release/acquire, monotonic counter) =====
        __syncthreads();
        if (tid == 0) {
            __threadfence();                      // release our h writes
            atomicAdd(&g_bar, 1u);
            const unsigned target = (unsigned)(t + 1) * NCTA;
            while (ld_acq(&g_bar) < target) { __nanosleep(64); }
        }
        __syncthreads();

        // ===== phase 2a: stage h_{t+1} (and x_{t+1}) into SMEM =====
        for (int idx = tid; idx < UB * HH; idx += NTHR) {
            int b = idx >> 9, k = idx & 511;
            hx[b * HXST + II + k] = __ldcg(&g_Hbuf[p1][(b0 + b) * HH + k]);
        }
        if (t + 1 < TT) {
            for (int idx = tid; idx < UB * II; idx += NTHR) {
                int b = idx >> 7, k = idx & 127;
                hx[b * HXST + k] = x[((size_t)(b0 + b) * TT + (t + 1)) * II + k];
            }
        }
        __syncthreads();

        // ===== phase 2b: fe = exp(h @ Wf^T + bf); c *= fe =====
        ull s0 = 0, s1 = 0, s2 = 0, s3 = 0;
        #pragma unroll 4
        for (int q = 0; q < HH / 4; q++) {
            float4 w = __ldg(&wfrow[q]);
            ull w01 = pack2(w.x, w.y);
            ull w23 = pack2(w.z, w.w);
            s0 = ffma2(w01, hloH[2 * q],     s0);
            s1 = ffma2(w23, hloH[2 * q + 1], s1);
            s2 = ffma2(w01, hhiH[2 * q],     s2);
            s3 = ffma2(w23, hhiH[2 * q + 1], s3);
        }
        c_lo *= expf(red2(s0) + red2(s1) + bfj);
        c_hi *= expf(red2(s2) + red2(s3) + bfj);
    }

    // ===== final h, c (tuple flatten: out | h | c) =====
    if (out_elems >= (long long)BB * TT * HH + 2LL * BB * HH) {
        float* hout = out + (size_t)BB * TT * HH;
        float* cout = hout + (size_t)BB * HH;
        hout[gblo * HH + j] = h_lo;
        hout[gbhi * HH + j] = h_hi;
        cout[gblo * HH + j] = c_lo;
        cout[gbhi * HH + j] = c_hi;
    }
}

extern "C" void kernel_launch(void* const* d_in, const int* in_sizes, int n_in,
                              void* d_out, int out_size) {
    const float* x    = (const float*)d_in[0];
    const float* W_ih = (const float*)d_in[1];
    const float* W_hh = (const float*)d_in[2];
    const float* b_ih = (const float*)d_in[3];
    const float* b_hh = (const float*)d_in[4];
    const float* Wf   = (const float*)d_in[5];
    const float* bf   = (const float*)d_in[6];
    // d_in[7] = Wi, d_in[8] = bi: unused by the reference recurrence
    float* out = (float*)d_out;

    const size_t smem_bytes = (size_t)(64 * WST + UB * HXST) * sizeof(float); // 205,440 B
    cudaFuncSetAttribute(sLSTM_70772471103948_kernel,
                         cudaFuncAttributeMaxDynamicSharedMemorySize, (int)smem_bytes);

    slstm_init_kernel<<<1, 1>>>();
    sLSTM_70772471103948_kernel<<<NCTA, NTHR, smem_bytes>>>(
        x, W_ih, W_hh, b_ih, b_hh, Wf, bf, out, (long long)out_size);
}

// round 6
// speedup vs baseline: 1.4481x; 1.4481x over previous
#include <cuda_runtime.h>
#include <cstddef>

// ---------------- problem constants ----------------
#define BB   64
#define TT   1024
#define II   128
#define HH   512
#define KK   640            // I + H

// ---------------- partitioning ----------------
#define GH   32             // hidden groups
#define GB   4              // batch groups
#define NCTA (GH*GB)        // 128 CTAs, one per SM, all resident
#define UH   16             // hidden units per CTA
#define UB   16             // batches per CTA
#define NTHR 256            // 16 u x 8 bp x 2 ks  (8 warps)

#define WST  642            // smem row stride (floats), even + 2-bank skew
#define HXST 642
#define KHALF 160           // f32x2 elements per k-split half (640/2/2)

typedef unsigned long long ull;

// persistent state (no cudaMalloc allowed)
__device__ float        g_Hbuf[2][BB*HH];
__device__ unsigned int g_bar[GB * 32];   // one counter per batch group, separate lines

// ---------------- packed fp32x2 helpers (Blackwell) ----------------
__device__ __forceinline__ ull ffma2(ull a, ull b, ull c) {
    ull d;
    asm("fma.rn.f32x2 %0, %1, %2, %3;" : "=l"(d) : "l"(a), "l"(b), "l"(c));
    return d;
}
__device__ __forceinline__ ull pack2(float lo, float hi) {
    ull d; asm("mov.b64 %0, {%1, %2};" : "=l"(d) : "f"(lo), "f"(hi)); return d;
}
__device__ __forceinline__ float red2(ull v) {
    return __uint_as_float((unsigned)v) + __uint_as_float((unsigned)(v >> 32));
}
__device__ __forceinline__ float sigm(float x) { return 1.0f / (1.0f + expf(-x)); }

__device__ __forceinline__ unsigned ld_acq(const unsigned* p) {
    unsigned v;
    asm volatile("ld.acquire.gpu.global.u32 %0, [%1];" : "=r"(v) : "l"(p) : "memory");
    return v;
}

__global__ void slstm_init_kernel() {
    if (threadIdx.x < GB) g_bar[threadIdx.x * 32] = 0u;
}

// ---------------- persistent sLSTM kernel ----------------
extern "C" __global__ void __launch_bounds__(NTHR, 1)
sLSTM_70772471103948_kernel(const float* __restrict__ x,     // [B,T,I]
                            const float* __restrict__ W_ih,  // [4H,I]
                            const float* __restrict__ W_hh,  // [4H,H]
                            const float* __restrict__ b_ih,  // [4H]
                            const float* __restrict__ b_hh,  // [4H]
                            const float* __restrict__ Wf,    // [H,H]
                            const float* __restrict__ bf,    // [H]
                            float* __restrict__ out,         // [B,T,H] | h[B,H] | c[B,H]
                            long long out_elems)
{
    extern __shared__ float smem[];
    float* Wsm   = smem;                         // 64 rows x WST
    float* hx    = smem + 64 * WST;              // 16 batches x HXST ([x_t | h_t])
    float* red1  = hx + UB * HXST;               // 128 x 8  phase-1 partials (ks=1)
    float* redfe = red1 + 128 * 8;               // 128 x 2  fe partials (ks=1)

    const int tid = threadIdx.x;
    const int u   = tid & 15;                    // local hidden unit
    const int bp  = (tid >> 4) & 7;              // batch pair 0..7
    const int ks  = tid >> 7;                    // k-split half 0/1
    const int hg  = blockIdx.x & (GH - 1);
    const int bg  = blockIdx.x >> 5;
    const int j0  = hg * UH;
    const int b0  = bg * UB;
    const int j   = j0 + u;
    const int blo = bp, bhi = bp + 8;
    const int gblo = b0 + blo, gbhi = b0 + bhi;
    const int lt  = tid & 127;                   // id within ks-half

    // ---- stage gate weights into SMEM once ----
    for (int idx = tid; idx < 64 * KK; idx += NTHR) {
        int r  = idx / KK;
        int k  = idx - r * KK;
        int gg = r >> 4, uu = r & 15;
        int grow = gg * HH + j0 + uu;            // gate order: i,f,g,o
        float w = (k < II) ? W_ih[grow * II + k] : W_hh[grow * HH + (k - II)];
        Wsm[r * WST + k] = w;
    }
    // ---- stage x_0 ; h_0 = 0 ----
    for (int idx = tid; idx < UB * II; idx += NTHR) {
        int b = idx >> 7, k = idx & 127;
        hx[b * HXST + k] = x[((size_t)(b0 + b) * TT + 0) * II + k];
    }
    for (int idx = tid; idx < UB * HH; idx += NTHR) {
        int b = idx >> 9, k = idx & 511;
        hx[b * HXST + II + k] = 0.0f;
    }
    float bias0 = b_ih[0 * HH + j] + b_hh[0 * HH + j];
    float bias1 = b_ih[1 * HH + j] + b_hh[1 * HH + j];
    float bias2 = b_ih[2 * HH + j] + b_hh[2 * HH + j];
    float bias3 = b_ih[3 * HH + j] + b_hh[3 * HH + j];
    const float bfj = bf[j];

    __syncthreads();

    const ull* wiR  = (const ull*)(Wsm + (0 * 16 + u) * WST) + ks * KHALF;
    const ull* wfR  = (const ull*)(Wsm + (1 * 16 + u) * WST) + ks * KHALF;
    const ull* wgR  = (const ull*)(Wsm + (2 * 16 + u) * WST) + ks * KHALF;
    const ull* woR  = (const ull*)(Wsm + (3 * 16 + u) * WST) + ks * KHALF;
    const ull* hloR = (const ull*)(hx + blo * HXST) + ks * KHALF;
    const ull* hhiR = (const ull*)(hx + bhi * HXST) + ks * KHALF;
    const ull* hloH = (const ull*)(hx + blo * HXST + II) + ks * (HH / 4);
    const ull* hhiH = (const ull*)(hx + bhi * HXST + II) + ks * (HH / 4);
    const float4* wfrow = (const float4*)(Wf + (size_t)j * HH) + ks * (HH / 8);

    unsigned int* mybar = &g_bar[bg * 32];

    float c_lo = 0.f, c_hi = 0.f, h_lo = 0.f, h_hi = 0.f;   // live in ks==0 threads

    #pragma unroll 1
    for (int t = 0; t < TT; t++) {
        // ===== phase 1: gate GEMM over this thread's k-half =====
        ull ai0 = 0, af0 = 0, ag0 = 0, ao0 = 0;
        ull ai1 = 0, af1 = 0, ag1 = 0, ao1 = 0;
        #pragma unroll 4
        for (int kk = 0; kk < KHALF; kk++) {
            ull v0 = hloR[kk];
            ull v1 = hhiR[kk];
            ull w0 = wiR[kk], w1 = wfR[kk], w2 = wgR[kk], w3 = woR[kk];
            ai0 = ffma2(w0, v0, ai0);  ai1 = ffma2(w0, v1, ai1);
            af0 = ffma2(w1, v0, af0);  af1 = ffma2(w1, v1, af1);
            ag0 = ffma2(w2, v0, ag0);  ag1 = ffma2(w2, v1, ag1);
            ao0 = ffma2(w3, v0, ao0);  ao1 = ffma2(w3, v1, ao1);
        }
        if (ks) {                                 // publish partials
            float* r = red1 + lt * 8;
            r[0] = red2(ai0); r[1] = red2(af0); r[2] = red2(ag0); r[3] = red2(ao0);
            r[4] = red2(ai1); r[5] = red2(af1); r[6] = red2(ag1); r[7] = red2(ao1);
        }
        __syncthreads();                          // S1

        const int p1 = (t + 1) & 1;
        if (!ks) {
            const float* r = red1 + lt * 8;
            float gi = red2(ai0) + r[0] + bias0, gf = red2(af0) + r[1] + bias1;
            float gg = red2(ag0) + r[2] + bias2, go = red2(ao0) + r[3] + bias3;
            float iv = sigm(gi), fv = sigm(gf), gv = tanhf(gg), ov = sigm(go);
            c_lo = fv * c_lo + iv * gv;
            h_lo = ov * tanhf(c_lo);
            gi = red2(ai1) + r[4] + bias0; gf = red2(af1) + r[5] + bias1;
            gg = red2(ag1) + r[6] + bias2; go = red2(ao1) + r[7] + bias3;
            iv = sigm(gi); fv = sigm(gf); gv = tanhf(gg); ov = sigm(go);
            c_hi = fv * c_hi + iv * gv;
            h_hi = ov * tanhf(c_hi);

            out[((size_t)gblo * TT + t) * HH + j] = h_lo;
            out[((size_t)gbhi * TT + t) * HH + j] = h_hi;
            __stcg(&g_Hbuf[p1][gblo * HH + j], h_lo);
            __stcg(&g_Hbuf[p1][gbhi * HH + j], h_hi);
        }

        // prefetch x_{t+1} into SMEM (independent of the barrier)
        if (t + 1 < TT) {
            #pragma unroll
            for (int it = 0; it < (UB * II) / NTHR; it++) {
                int idx = tid + it * NTHR;
                int b = idx >> 7, k = idx & 127;
                hx[b * HXST + k] = x[((size_t)(b0 + b) * TT + (t + 1)) * II + k];
            }
        }
        __syncthreads();                          // S2 (h stores done CTA-wide)

        // ===== per-batch-group grid barrier (32 CTAs) =====
        if (tid == 0) {
            __threadfence();                      // release h writes
            atomicAdd(mybar, 1u);
            const unsigned target = (unsigned)(t + 1) * GH;
            while (ld_acq(mybar) < target) { }
        }
        __syncthreads();                          // S3

        // ===== stage h_{t+1} into SMEM =====
        #pragma unroll
        for (int it = 0; it < (UB * HH) / NTHR; it++) {
            int idx = tid + it * NTHR;
            int b = idx >> 9, k = idx & 511;
            hx[b * HXST + II + k] = __ldcg(&g_Hbuf[p1][(b0 + b) * HH + k]);
        }
        __syncthreads();                          // S4

        // ===== phase 2b: fe = exp(h @ Wf^T + bf); c *= fe (k-split) =====
        ull s0 = 0, s1 = 0, s2 = 0, s3 = 0;
        #pragma unroll 4
        for (int q = 0; q < HH / 8; q++) {
            float4 w = __ldg(&wfrow[q]);
            ull w01 = pack2(w.x, w.y);
            ull w23 = pack2(w.z, w.w);
            s0 = ffma2(w01, hloH[2 * q],     s0);
            s1 = ffma2(w23, hloH[2 * q + 1], s1);
            s2 = ffma2(w01, hhiH[2 * q],     s2);
            s3 = ffma2(w23, hhiH[2 * q + 1], s3);
        }
        if (ks) {
            redfe[lt * 2 + 0] = red2(s0) + red2(s1);
            redfe[lt * 2 + 1] = red2(s2) + red2(s3);
        }
        __syncthreads();                          // S5
        if (!ks) {
            c_lo *= expf(red2(s0) + red2(s1) + redfe[lt * 2 + 0] + bfj);
            c_hi *= expf(red2(s2) + red2(s3) + redfe[lt * 2 + 1] + bfj);
        }
    }

    // ===== final h, c (tuple flatten: out | h | c) =====
    if (!ks && out_elems >= (long long)BB * TT * HH + 2LL * BB * HH) {
        float* hout = out + (size_t)BB * TT * HH;
        float* cout = hout + (size_t)BB * HH;
        hout[gblo * HH + j] = h_lo;
        hout[gbhi * HH + j] = h_hi;
        cout[gblo * HH + j] = c_lo;
        cout[gbhi * HH + j] = c_hi;
    }
}

extern "C" void kernel_launch(void* const* d_in, const int* in_sizes, int n_in,
                              void* d_out, int out_size) {
    const float* x    = (const float*)d_in[0];
    const float* W_ih = (const float*)d_in[1];
    const float* W_hh = (const float*)d_in[2];
    const float* b_ih = (const float*)d_in[3];
    const float* b_hh = (const float*)d_in[4];
    const float* Wf   = (const float*)d_in[5];
    const float* bf   = (const float*)d_in[6];
    // d_in[7] = Wi, d_in[8] = bi: unused by the reference recurrence
    float* out = (float*)d_out;

    const size_t smem_bytes =
        (size_t)(64 * WST + UB * HXST + 128 * 8 + 128 * 2) * sizeof(float); // 210,560 B
    cudaFuncSetAttribute(sLSTM_70772471103948_kernel,
                         cudaFuncAttributeMaxDynamicSharedMemorySize, (int)smem_bytes);

    slstm_init_kernel<<<1, 32>>>();
    sLSTM_70772471103948_kernel<<<NCTA, NTHR, smem_bytes>>>(
        x, W_ih, W_hh, b_ih, b_hh, Wf, bf, out, (long long)out_size);
}